// round 9
// baseline (speedup 1.0000x reference)
#include <cuda_runtime.h>
#include <cuda_fp16.h>
#include <cstdint>

// Problem constants (shapes are fixed by the dataset)
#define MAXN 100000
#define MAXE 1600000
#define HDIM 64
#define SCAN_B 1024

// ---------------- scratch (no allocations allowed -> __device__ globals) ----
__device__ int    g_deg[MAXN];                 // zero at load; re-zeroed by scanA
__device__ float  g_dinv[MAXN];
__device__ int    g_rowstart[MAXN + 1];
__device__ int    g_cursor[MAXN];
__device__ int    g_esrc[MAXE];
__device__ int    g_blocksum[1024];
__device__ __half g_hs[(size_t)MAXN * HDIM];   // fp16: 128B/row -> 2 edges/warp
__device__ float  g_y[(size_t)MAXN * HDIM];

// ---------------- f32x2 helpers (Blackwell packed fp32) ---------------------
__device__ __forceinline__ unsigned long long pack2(float x, float y) {
    unsigned long long r;
    asm("mov.b64 %0, {%1,%2};" : "=l"(r) : "f"(x), "f"(y));
    return r;
}
__device__ __forceinline__ unsigned long long ffma2(unsigned long long a,
                                                    unsigned long long b,
                                                    unsigned long long c) {
    unsigned long long d;
    asm("fma.rn.f32x2 %0, %1, %2, %3;" : "=l"(d) : "l"(a), "l"(b), "l"(c));
    return d;
}
__device__ __forceinline__ unsigned long long add2(unsigned long long a,
                                                   unsigned long long b) {
    unsigned long long d;
    asm("add.rn.f32x2 %0, %1, %2;" : "=l"(d) : "l"(a), "l"(b));
    return d;
}
__device__ __forceinline__ unsigned long long mul2(unsigned long long a,
                                                   unsigned long long b) {
    unsigned long long d;
    asm("mul.rn.f32x2 %0, %1, %2;" : "=l"(d) : "l"(a), "l"(b));
    return d;
}
__device__ __forceinline__ float2 unpack2(unsigned long long v) {
    float2 f;
    asm("mov.b64 {%0,%1}, %2;" : "=f"(f.x), "=f"(f.y) : "l"(v));
    return f;
}
__device__ __forceinline__ void lds_v2u64(unsigned addr, unsigned long long& a,
                                          unsigned long long& b) {
    asm("ld.shared.v2.u64 {%0,%1}, [%2];" : "=l"(a), "=l"(b) : "r"(addr));
}
// add 4 fp16 values (one u64) into 2 packed-f32x2 accumulators
__device__ __forceinline__ void acc_h4(unsigned long long v,
                                       unsigned long long& a01,
                                       unsigned long long& a23) {
    const unsigned lo = (unsigned)v, hi = (unsigned)(v >> 32);
    const float2 f0 = __half22float2(*reinterpret_cast<const __half2*>(&lo));
    const float2 f1 = __half22float2(*reinterpret_cast<const __half2*>(&hi));
    a01 = add2(a01, pack2(f0.x, f0.y));
    a23 = add2(a23, pack2(f1.x, f1.y));
}

// ---------------- CSR build --------------------------------------------------
__global__ void count_deg_kernel(const int* __restrict__ dst, int e) {
    int i = blockIdx.x * blockDim.x + threadIdx.x;
    if (i < e) atomicAdd(&g_deg[dst[i]], 1);
}

// Phase A: per-block exclusive scan of g_deg; fused dinv; re-zero deg.
__global__ void __launch_bounds__(SCAN_B)
scanA_kernel(int n) {
    __shared__ int sh[SCAN_B];
    const int t = threadIdx.x;
    const int i = blockIdx.x * SCAN_B + t;
    const int v = (i < n) ? g_deg[i] : 0;
    if (i < n) {
        g_dinv[i] = rsqrtf((float)v + 1.0f);
        g_deg[i] = 0;                       // ready for next replay
    }
    sh[t] = v;
    __syncthreads();
    int acc = v;
#pragma unroll
    for (int off = 1; off < SCAN_B; off <<= 1) {
        int u = (t >= off) ? sh[t - off] : 0;
        __syncthreads();
        acc += u;
        sh[t] = acc;
        __syncthreads();
    }
    if (i < n) g_rowstart[i] = acc - v;     // local exclusive
    if (t == SCAN_B - 1) g_blocksum[blockIdx.x] = acc;
}

// Phase C (with folded block-offset scan): each block warp-reduces the
// prefix of blocksums itself, then writes rowstart and cursor (+sentinel).
__global__ void __launch_bounds__(SCAN_B)
scanC_kernel(int n, int e) {
    __shared__ int s_off;
    const int t = threadIdx.x;
    const int bid = blockIdx.x;
    if (t < 32) {
        int s = 0;
        for (int j = t; j < bid; j += 32) s += g_blocksum[j];  // <= 4 iters
#pragma unroll
        for (int o = 16; o > 0; o >>= 1)
            s += __shfl_xor_sync(0xffffffffu, s, o);
        if (t == 0) s_off = s;
    }
    __syncthreads();
    const int i = bid * SCAN_B + t;
    if (i < n) {
        const int r = g_rowstart[i] + s_off;
        g_rowstart[i] = r;
        g_cursor[i]   = r;
    }
    if (i == 0) g_rowstart[n] = e;
}

__global__ void place_kernel(const int* __restrict__ src,
                             const int* __restrict__ dst, int e) {
    int i = blockIdx.x * blockDim.x + threadIdx.x;
    if (i < e) {
        int d = dst[i];
        int pos = atomicAdd(&g_cursor[d], 1);
        g_esrc[pos] = src[i];
    }
}

// ---------------- GEMM: hs[row] = fp16( (X[row] @ W) * dinv[row] ) ----------
// TWO rows per thread; W broadcast from smem; fp32 f32x2 accumulation,
// converted to fp16 only at the store.
template <int KDIM>
__global__ void __launch_bounds__(128, 1)
gemm_hs_kernel(const float* __restrict__ X, const float* __restrict__ W, int n) {
    __shared__ float Ws[KDIM * HDIM];
    for (int i = threadIdx.x; i < KDIM * HDIM / 4; i += 128)
        ((float4*)Ws)[i] = ((const float4*)W)[i];
    __syncthreads();

    const int row0 = blockIdx.x * 256 + threadIdx.x;
    const int row1 = row0 + 128;
    if (row0 >= n) return;
    const bool has1 = (row1 < n);

    unsigned long long acc0[32], acc1[32];
#pragma unroll
    for (int p = 0; p < 32; p++) { acc0[p] = 0ull; acc1[p] = 0ull; }

    const float4* xr0 = (const float4*)(X + (size_t)row0 * KDIM);
    const float4* xr1 = (const float4*)(X + (size_t)(has1 ? row1 : row0) * KDIM);
    const unsigned wsh = (unsigned)__cvta_generic_to_shared(Ws);

#pragma unroll 1
    for (int kc = 0; kc < KDIM / 4; kc++) {
        const float4 a0 = xr0[kc];
        const float4 a1 = xr1[kc];
        const float* av0 = reinterpret_cast<const float*>(&a0);
        const float* av1 = reinterpret_cast<const float*>(&a1);
#pragma unroll
        for (int kk = 0; kk < 4; kk++) {
            const unsigned long long ap0 = pack2(av0[kk], av0[kk]);
            const unsigned long long ap1 = pack2(av1[kk], av1[kk]);
            const unsigned baddr = wsh + (unsigned)((kc * 4 + kk) * HDIM) * 4u;
#pragma unroll
            for (int p = 0; p < 16; p++) {
                unsigned long long b0, b1;
                lds_v2u64(baddr + p * 16u, b0, b1);
                acc0[2 * p]     = ffma2(ap0, b0, acc0[2 * p]);
                acc0[2 * p + 1] = ffma2(ap0, b1, acc0[2 * p + 1]);
                acc1[2 * p]     = ffma2(ap1, b0, acc1[2 * p]);
                acc1[2 * p + 1] = ffma2(ap1, b1, acc1[2 * p + 1]);
            }
        }
    }

    {
        const float dv = __ldg(&g_dinv[row0]);
        const unsigned long long dp = pack2(dv, dv);
        uint4* op = (uint4*)(g_hs + (size_t)row0 * HDIM);
#pragma unroll
        for (int v = 0; v < 8; v++) {
            uint4 w;
            __half2 h;
            h = __float22half2_rn(unpack2(mul2(acc0[4 * v + 0], dp))); w.x = *(unsigned*)&h;
            h = __float22half2_rn(unpack2(mul2(acc0[4 * v + 1], dp))); w.y = *(unsigned*)&h;
            h = __float22half2_rn(unpack2(mul2(acc0[4 * v + 2], dp))); w.z = *(unsigned*)&h;
            h = __float22half2_rn(unpack2(mul2(acc0[4 * v + 3], dp))); w.w = *(unsigned*)&h;
            op[v] = w;
        }
    }
    if (has1) {
        const float dv = __ldg(&g_dinv[row1]);
        const unsigned long long dp = pack2(dv, dv);
        uint4* op = (uint4*)(g_hs + (size_t)row1 * HDIM);
#pragma unroll
        for (int v = 0; v < 8; v++) {
            uint4 w;
            __half2 h;
            h = __float22half2_rn(unpack2(mul2(acc1[4 * v + 0], dp))); w.x = *(unsigned*)&h;
            h = __float22half2_rn(unpack2(mul2(acc1[4 * v + 1], dp))); w.y = *(unsigned*)&h;
            h = __float22half2_rn(unpack2(mul2(acc1[4 * v + 2], dp))); w.z = *(unsigned*)&h;
            h = __float22half2_rn(unpack2(mul2(acc1[4 * v + 3], dp))); w.w = *(unsigned*)&h;
            op[v] = w;
        }
    }
}

// ---------------- gather + self-loop + bias + LayerNorm + GELU (+ head) -----
// One warp per node, fp16 hs rows (128B). Half-warp h = lane>>4 handles edge
// i+h of each pair; lane q = lane&15 owns cols 4q..4q+3 (8B LDG); packed
// f32x2 accumulation.
template <bool FINAL>
__global__ void __launch_bounds__(256)
gather_finalize_kernel(const float* __restrict__ b, const float* __restrict__ g,
                       const float* __restrict__ be, const float* __restrict__ Wh,
                       const float* __restrict__ bh, float* __restrict__ out,
                       int n) {
    const int warp = (blockIdx.x * blockDim.x + threadIdx.x) >> 5;
    const int lane = threadIdx.x & 31;
    if (warp >= n) return;
    const int node = warp;
    const int h = lane >> 4;       // which edge of the pair
    const int q = lane & 15;       // column block (4 halves = 8B)

    const int s0 = g_rowstart[node];
    const int s1 = g_rowstart[node + 1];

    const unsigned long long* hsp = (const unsigned long long*)g_hs;  // 16 u64/row

    unsigned long long aA01 = 0ull, aA23 = 0ull;
    unsigned long long aB01 = 0ull, aB23 = 0ull;

    for (int e = s0; e < s1; e += 32) {
        const int cnt = min(32, s1 - e);
        const int s = (lane < cnt) ? __ldg(&g_esrc[e + lane]) : 0;
        int i = 0;
        for (; i + 4 <= cnt; i += 4) {           // 2 pairs = 4 edges per iter
            const int sa = __shfl_sync(0xffffffffu, s, i + h);
            const int sb = __shfl_sync(0xffffffffu, s, i + 2 + h);
            const unsigned long long va = __ldg(&hsp[(size_t)sa * 16 + q]);
            const unsigned long long vb = __ldg(&hsp[(size_t)sb * 16 + q]);
            acc_h4(va, aA01, aA23);
            acc_h4(vb, aB01, aB23);
        }
        for (; i < cnt; i += 2) {                // pair tail
            const int idx = i + h;
            const int sa = __shfl_sync(0xffffffffu, s, idx & 31);
            if (idx < cnt)
                acc_h4(__ldg(&hsp[(size_t)sa * 16 + q]), aA01, aA23);
        }
    }

    // self-loop term: add once (half-warp A only)
    if (h == 0)
        acc_h4(__ldg(&hsp[(size_t)node * 16 + q]), aA01, aA23);

    aA01 = add2(aA01, aB01);
    aA23 = add2(aA23, aB23);
    const float2 p01 = unpack2(aA01);
    const float2 p23 = unpack2(aA23);
    float4 accA = make_float4(p01.x, p01.y, p23.x, p23.y);
    // combine the two half-warps (same q in lane l and l^16)
    accA.x += __shfl_xor_sync(0xffffffffu, accA.x, 16);
    accA.y += __shfl_xor_sync(0xffffffffu, accA.y, 16);
    accA.z += __shfl_xor_sync(0xffffffffu, accA.z, 16);
    accA.w += __shfl_xor_sync(0xffffffffu, accA.w, 16);

    const float dv = g_dinv[node];
    const float4 b4 = __ldg(&((const float4*)b)[q]);
    float v0 = dv * accA.x + b4.x;
    float v1 = dv * accA.y + b4.y;
    float v2 = dv * accA.z + b4.z;
    float v3 = dv * accA.w + b4.w;

    // LayerNorm over 64 values (4 per lane, 16-lane groups; halves duplicate)
    float s  = v0 + v1 + v2 + v3;
    float sq = v0 * v0 + v1 * v1 + v2 * v2 + v3 * v3;
#pragma unroll
    for (int o = 8; o > 0; o >>= 1) {
        s  += __shfl_xor_sync(0xffffffffu, s, o);
        sq += __shfl_xor_sync(0xffffffffu, sq, o);
    }
    const float mu   = s * (1.0f / 64.0f);
    float var        = sq * (1.0f / 64.0f) - mu * mu;
    const float rstd = rsqrtf(var + 1e-5f);

    const float4 g4  = __ldg(&((const float4*)g)[q]);
    const float4 be4 = __ldg(&((const float4*)be)[q]);
    float u0 = (v0 - mu) * rstd * g4.x + be4.x;
    float u1 = (v1 - mu) * rstd * g4.y + be4.y;
    float u2 = (v2 - mu) * rstd * g4.z + be4.z;
    float u3 = (v3 - mu) * rstd * g4.w + be4.w;

    // exact-erf GELU
    const float k = 0.70710678118654752f;
    u0 = 0.5f * u0 * (1.0f + erff(u0 * k));
    u1 = 0.5f * u1 * (1.0f + erff(u1 * k));
    u2 = 0.5f * u2 * (1.0f + erff(u2 * k));
    u3 = 0.5f * u3 * (1.0f + erff(u3 * k));

    if (FINAL) {
        const float4 w4 = __ldg(&((const float4*)Wh)[q]);
        float p = u0 * w4.x + u1 * w4.y + u2 * w4.z + u3 * w4.w;
#pragma unroll
        for (int o = 8; o > 0; o >>= 1) p += __shfl_xor_sync(0xffffffffu, p, o);
        if (lane == 0) out[node] = p + __ldg(&bh[0]);
    } else {
        if (h == 0)
            ((float4*)out)[(size_t)node * 16 + q] = make_float4(u0, u1, u2, u3);
    }
}

// ---------------- launch -----------------------------------------------------
extern "C" void kernel_launch(void* const* d_in, const int* in_sizes, int n_in,
                              void* d_out, int out_size) {
    const float* x   = (const float*)d_in[0];
    const int*   ei  = (const int*)d_in[1];
    const float* W1  = (const float*)d_in[2];
    const float* b1  = (const float*)d_in[3];
    const float* g1  = (const float*)d_in[4];
    const float* be1 = (const float*)d_in[5];
    const float* W2  = (const float*)d_in[6];
    const float* b2  = (const float*)d_in[7];
    const float* g2  = (const float*)d_in[8];
    const float* be2 = (const float*)d_in[9];
    const float* W3  = (const float*)d_in[10];
    const float* b3  = (const float*)d_in[11];
    const float* g3  = (const float*)d_in[12];
    const float* be3 = (const float*)d_in[13];
    const float* Wh  = (const float*)d_in[14];
    const float* bh  = (const float*)d_in[15];
    float* out = (float*)d_out;

    const int n = in_sizes[0] / 128;
    const int e = in_sizes[1] / 2;
    const int* srcs = ei;
    const int* dsts = ei + e;

    static float* y = nullptr;
    static cudaStream_t s2 = nullptr;
    static cudaEvent_t ev_fork = nullptr, ev_csr = nullptr;
    if (!y) {
        cudaGetSymbolAddress((void**)&y, g_y);
        cudaStreamCreate(&s2);
        cudaEventCreateWithFlags(&ev_fork, cudaEventDisableTiming);
        cudaEventCreateWithFlags(&ev_csr, cudaEventDisableTiming);
    }

    const int EB = (e + 255) / 256;
    const int SB = (n + SCAN_B - 1) / SCAN_B;  // scan blocks (<= 98)
    const int GB = (n + 255) / 256;            // gemm blocks (2 rows/thread)
    const int WB = (n + 7) / 8;                // gather blocks (8 warps/block)

    // CSR head (produces dinv, local scans)
    count_deg_kernel<<<EB, 256>>>(dsts, e);
    scanA_kernel<<<SB, SCAN_B>>>(n);           // + fused dinv + deg re-zero

    // Fork: CSR tail on s2 runs concurrently with gemm1 (gemm1 needs only dinv)
    cudaEventRecord(ev_fork, 0);
    cudaStreamWaitEvent(s2, ev_fork, 0);
    scanC_kernel<<<SB, SCAN_B, 0, s2>>>(n, e); // + folded scanB + cursor init
    place_kernel<<<EB, 256, 0, s2>>>(srcs, dsts, e);
    cudaEventRecord(ev_csr, s2);

    // Layer 1 GEMM (IN=128) on the main stream, concurrent with CSR tail
    gemm_hs_kernel<128><<<GB, 128>>>(x, W1, n);
    cudaStreamWaitEvent(0, ev_csr, 0);         // join before gather1

    gather_finalize_kernel<false><<<WB, 256>>>(b1, g1, be1, nullptr, nullptr, y, n);
    // Layer 2 (IN=64)
    gemm_hs_kernel<64><<<GB, 128>>>(y, W2, n);
    gather_finalize_kernel<false><<<WB, 256>>>(b2, g2, be2, nullptr, nullptr, y, n);
    // Layer 3 (IN=64) + fused head
    gemm_hs_kernel<64><<<GB, 128>>>(y, W3, n);
    gather_finalize_kernel<true><<<WB, 256>>>(b3, g3, be3, Wh, bh, out, n);
}

// round 10
// speedup vs baseline: 1.0593x; 1.0593x over previous
#include <cuda_runtime.h>
#include <cuda_fp16.h>
#include <cstdint>

// Problem constants (shapes are fixed by the dataset)
#define MAXN 100000
#define MAXE 1600000
#define HDIM 64
#define SCAN_B 1024

// ---------------- scratch (no allocations allowed -> __device__ globals) ----
__device__ int    g_deg[MAXN];                 // zero at load; re-zeroed by scanA
__device__ float  g_dinv[MAXN];
__device__ int    g_rowstart[MAXN + 1];
__device__ int    g_cursor[MAXN];
__device__ int    g_esrc[MAXE];
__device__ int    g_blocksum[1024];
__device__ __half g_hs[(size_t)MAXN * HDIM];   // fp16: 128B/row -> 2 edges/warp
__device__ float  g_y[(size_t)MAXN * HDIM];

// ---------------- helpers ----------------------------------------------------
__device__ __forceinline__ unsigned long long pack2(float x, float y) {
    unsigned long long r;
    asm("mov.b64 %0, {%1,%2};" : "=l"(r) : "f"(x), "f"(y));
    return r;
}
__device__ __forceinline__ unsigned long long add2(unsigned long long a,
                                                   unsigned long long b) {
    unsigned long long d;
    asm("add.rn.f32x2 %0, %1, %2;" : "=l"(d) : "l"(a), "l"(b));
    return d;
}
__device__ __forceinline__ float2 unpack2(unsigned long long v) {
    float2 f;
    asm("mov.b64 {%0,%1}, %2;" : "=f"(f.x), "=f"(f.y) : "l"(v));
    return f;
}
__device__ __forceinline__ unsigned f2tf32(float x) {
    unsigned r;
    asm("cvt.rna.tf32.f32 %0, %1;" : "=r"(r) : "f"(x));
    return r;
}
__device__ __forceinline__ void mma_tf32(float& c0, float& c1, float& c2, float& c3,
                                         unsigned a0, unsigned a1, unsigned a2,
                                         unsigned a3, unsigned b0, unsigned b1) {
    asm("mma.sync.aligned.m16n8k8.row.col.f32.tf32.tf32.f32 "
        "{%0,%1,%2,%3}, {%4,%5,%6,%7}, {%8,%9}, {%0,%1,%2,%3};"
        : "+f"(c0), "+f"(c1), "+f"(c2), "+f"(c3)
        : "r"(a0), "r"(a1), "r"(a2), "r"(a3), "r"(b0), "r"(b1));
}
// add 4 fp16 values (one u64) into 2 packed-f32x2 accumulators
__device__ __forceinline__ void acc_h4(unsigned long long v,
                                       unsigned long long& a01,
                                       unsigned long long& a23) {
    const unsigned lo = (unsigned)v, hi = (unsigned)(v >> 32);
    const float2 f0 = __half22float2(*reinterpret_cast<const __half2*>(&lo));
    const float2 f1 = __half22float2(*reinterpret_cast<const __half2*>(&hi));
    a01 = add2(a01, pack2(f0.x, f0.y));
    a23 = add2(a23, pack2(f1.x, f1.y));
}

// ---------------- CSR build --------------------------------------------------
__global__ void count_deg_kernel(const int* __restrict__ dst, int e) {
    int i = blockIdx.x * blockDim.x + threadIdx.x;
    if (i < e) atomicAdd(&g_deg[dst[i]], 1);
}

// Phase A: per-block exclusive scan of g_deg; fused dinv; re-zero deg.
__global__ void __launch_bounds__(SCAN_B)
scanA_kernel(int n) {
    __shared__ int sh[SCAN_B];
    const int t = threadIdx.x;
    const int i = blockIdx.x * SCAN_B + t;
    const int v = (i < n) ? g_deg[i] : 0;
    if (i < n) {
        g_dinv[i] = rsqrtf((float)v + 1.0f);
        g_deg[i] = 0;                       // ready for next replay
    }
    sh[t] = v;
    __syncthreads();
    int acc = v;
#pragma unroll
    for (int off = 1; off < SCAN_B; off <<= 1) {
        int u = (t >= off) ? sh[t - off] : 0;
        __syncthreads();
        acc += u;
        sh[t] = acc;
        __syncthreads();
    }
    if (i < n) g_rowstart[i] = acc - v;     // local exclusive
    if (t == SCAN_B - 1) g_blocksum[blockIdx.x] = acc;
}

// Phase C (with folded block-offset scan): each block warp-reduces the
// prefix of blocksums itself, then writes rowstart and cursor (+sentinel).
__global__ void __launch_bounds__(SCAN_B)
scanC_kernel(int n, int e) {
    __shared__ int s_off;
    const int t = threadIdx.x;
    const int bid = blockIdx.x;
    if (t < 32) {
        int s = 0;
        for (int j = t; j < bid; j += 32) s += g_blocksum[j];  // <= 4 iters
#pragma unroll
        for (int o = 16; o > 0; o >>= 1)
            s += __shfl_xor_sync(0xffffffffu, s, o);
        if (t == 0) s_off = s;
    }
    __syncthreads();
    const int i = bid * SCAN_B + t;
    if (i < n) {
        const int r = g_rowstart[i] + s_off;
        g_rowstart[i] = r;
        g_cursor[i]   = r;
    }
    if (i == 0) g_rowstart[n] = e;
}

__global__ void place_kernel(const int* __restrict__ src,
                             const int* __restrict__ dst, int e) {
    int i = blockIdx.x * blockDim.x + threadIdx.x;
    if (i < e) {
        int d = dst[i];
        int pos = atomicAdd(&g_cursor[d], 1);
        g_esrc[pos] = src[i];
    }
}

// ---------------- GEMM (tensor cores): hs = fp16((X @ W) * dinv) -------------
// mma.sync.m16n8k8 tf32. Block = 128 thr / 4 warps / 64 rows (16 per warp).
// X tile and W staged in smem pre-converted to tf32, strides padded +4 floats
// (bank pattern (4g+t) mod 32 covers all banks -> conflict-free frag loads).
template <int KDIM>
__global__ void __launch_bounds__(128)
gemm_tf32_kernel(const float* __restrict__ X, const float* __restrict__ W, int n) {
    constexpr int SX = KDIM + 4;      // Xs stride (floats)
    constexpr int SW = HDIM + 4;      // Ws stride (floats)
    extern __shared__ unsigned sm[];
    unsigned* Xs = sm;                 // 64 rows x SX
    unsigned* Ws = sm + 64 * SX;       // KDIM rows x SW

    const int tid = threadIdx.x;
    const int rb  = blockIdx.x * 64;

    // Stage X tile (clamped rows) with tf32 conversion
    const float4* X4 = (const float4*)X;
    for (int idx = tid; idx < 64 * (KDIM / 4); idx += 128) {
        const int row = idx / (KDIM / 4);
        const int c4  = idx % (KDIM / 4);
        const int gr  = min(rb + row, n - 1);
        const float4 v = X4[(size_t)gr * (KDIM / 4) + c4];
        unsigned* d = Xs + row * SX + c4 * 4;
        d[0] = f2tf32(v.x); d[1] = f2tf32(v.y);
        d[2] = f2tf32(v.z); d[3] = f2tf32(v.w);
    }
    // Stage W with tf32 conversion
    const float4* W4 = (const float4*)W;
    for (int idx = tid; idx < KDIM * (HDIM / 4); idx += 128) {
        const int k  = idx / (HDIM / 4);
        const int c4 = idx % (HDIM / 4);
        const float4 v = W4[(size_t)k * (HDIM / 4) + c4];
        unsigned* d = Ws + k * SW + c4 * 4;
        d[0] = f2tf32(v.x); d[1] = f2tf32(v.y);
        d[2] = f2tf32(v.z); d[3] = f2tf32(v.w);
    }
    __syncthreads();

    const int warp = tid >> 5;
    const int lane = tid & 31;
    const int g = lane >> 2;          // group id (row within half-tile)
    const int t = lane & 3;           // thread in group (k / col pairs)
    const unsigned* Xw = Xs + (warp * 16) * SX;

    float c[8][4];
#pragma unroll
    for (int nt = 0; nt < 8; nt++)
#pragma unroll
        for (int j = 0; j < 4; j++) c[nt][j] = 0.f;

#pragma unroll
    for (int ks = 0; ks < KDIM / 8; ks++) {
        const int kb = ks * 8;
        const unsigned a0 = Xw[g * SX + kb + t];
        const unsigned a1 = Xw[(g + 8) * SX + kb + t];
        const unsigned a2 = Xw[g * SX + kb + t + 4];
        const unsigned a3 = Xw[(g + 8) * SX + kb + t + 4];
#pragma unroll
        for (int nt = 0; nt < 8; nt++) {
            const unsigned b0 = Ws[(kb + t) * SW + nt * 8 + g];
            const unsigned b1 = Ws[(kb + t + 4) * SW + nt * 8 + g];
            mma_tf32(c[nt][0], c[nt][1], c[nt][2], c[nt][3],
                     a0, a1, a2, a3, b0, b1);
        }
    }

    // Epilogue: scale by dinv, convert to fp16, store (predicated tail)
    const int r0 = rb + warp * 16 + g;
    const int r1 = r0 + 8;
    const float d0 = __ldg(&g_dinv[min(r0, n - 1)]);
    const float d1 = __ldg(&g_dinv[min(r1, n - 1)]);
    __half2* hs2 = (__half2*)g_hs;     // 32 half2 per row
#pragma unroll
    for (int nt = 0; nt < 8; nt++) {
        const int cc = nt * 4 + t;     // half2 column index (col = 2*cc)
        if (r0 < n)
            hs2[(size_t)r0 * 32 + cc] =
                __floats2half2_rn(c[nt][0] * d0, c[nt][1] * d0);
        if (r1 < n)
            hs2[(size_t)r1 * 32 + cc] =
                __floats2half2_rn(c[nt][2] * d1, c[nt][3] * d1);
    }
}

// ---------------- gather + self-loop + bias + LayerNorm + GELU (+ head) -----
// One warp per node, fp16 hs rows (128B). Half-warp h = lane>>4 handles edge
// i+h of each pair; lane q = lane&15 owns cols 4q..4q+3 (8B LDG); packed
// f32x2 accumulation.
template <bool FINAL>
__global__ void __launch_bounds__(256)
gather_finalize_kernel(const float* __restrict__ b, const float* __restrict__ g,
                       const float* __restrict__ be, const float* __restrict__ Wh,
                       const float* __restrict__ bh, float* __restrict__ out,
                       int n) {
    const int warp = (blockIdx.x * blockDim.x + threadIdx.x) >> 5;
    const int lane = threadIdx.x & 31;
    if (warp >= n) return;
    const int node = warp;
    const int h = lane >> 4;       // which edge of the pair
    const int q = lane & 15;       // column block (4 halves = 8B)

    const int s0 = g_rowstart[node];
    const int s1 = g_rowstart[node + 1];

    const unsigned long long* hsp = (const unsigned long long*)g_hs;  // 16 u64/row

    unsigned long long aA01 = 0ull, aA23 = 0ull;
    unsigned long long aB01 = 0ull, aB23 = 0ull;

    for (int e = s0; e < s1; e += 32) {
        const int cnt = min(32, s1 - e);
        const int s = (lane < cnt) ? __ldg(&g_esrc[e + lane]) : 0;
        int i = 0;
        for (; i + 4 <= cnt; i += 4) {           // 2 pairs = 4 edges per iter
            const int sa = __shfl_sync(0xffffffffu, s, i + h);
            const int sb = __shfl_sync(0xffffffffu, s, i + 2 + h);
            const unsigned long long va = __ldg(&hsp[(size_t)sa * 16 + q]);
            const unsigned long long vb = __ldg(&hsp[(size_t)sb * 16 + q]);
            acc_h4(va, aA01, aA23);
            acc_h4(vb, aB01, aB23);
        }
        for (; i < cnt; i += 2) {                // pair tail
            const int idx = i + h;
            const int sa = __shfl_sync(0xffffffffu, s, idx & 31);
            if (idx < cnt)
                acc_h4(__ldg(&hsp[(size_t)sa * 16 + q]), aA01, aA23);
        }
    }

    // self-loop term: add once (half-warp A only)
    if (h == 0)
        acc_h4(__ldg(&hsp[(size_t)node * 16 + q]), aA01, aA23);

    aA01 = add2(aA01, aB01);
    aA23 = add2(aA23, aB23);
    const float2 p01 = unpack2(aA01);
    const float2 p23 = unpack2(aA23);
    float4 accA = make_float4(p01.x, p01.y, p23.x, p23.y);
    // combine the two half-warps (same q in lane l and l^16)
    accA.x += __shfl_xor_sync(0xffffffffu, accA.x, 16);
    accA.y += __shfl_xor_sync(0xffffffffu, accA.y, 16);
    accA.z += __shfl_xor_sync(0xffffffffu, accA.z, 16);
    accA.w += __shfl_xor_sync(0xffffffffu, accA.w, 16);

    const float dv = g_dinv[node];
    const float4 b4 = __ldg(&((const float4*)b)[q]);
    float v0 = dv * accA.x + b4.x;
    float v1 = dv * accA.y + b4.y;
    float v2 = dv * accA.z + b4.z;
    float v3 = dv * accA.w + b4.w;

    // LayerNorm over 64 values (4 per lane, 16-lane groups; halves duplicate)
    float s  = v0 + v1 + v2 + v3;
    float sq = v0 * v0 + v1 * v1 + v2 * v2 + v3 * v3;
#pragma unroll
    for (int o = 8; o > 0; o >>= 1) {
        s  += __shfl_xor_sync(0xffffffffu, s, o);
        sq += __shfl_xor_sync(0xffffffffu, sq, o);
    }
    const float mu   = s * (1.0f / 64.0f);
    float var        = sq * (1.0f / 64.0f) - mu * mu;
    const float rstd = rsqrtf(var + 1e-5f);

    const float4 g4  = __ldg(&((const float4*)g)[q]);
    const float4 be4 = __ldg(&((const float4*)be)[q]);
    float u0 = (v0 - mu) * rstd * g4.x + be4.x;
    float u1 = (v1 - mu) * rstd * g4.y + be4.y;
    float u2 = (v2 - mu) * rstd * g4.z + be4.z;
    float u3 = (v3 - mu) * rstd * g4.w + be4.w;

    // exact-erf GELU
    const float k = 0.70710678118654752f;
    u0 = 0.5f * u0 * (1.0f + erff(u0 * k));
    u1 = 0.5f * u1 * (1.0f + erff(u1 * k));
    u2 = 0.5f * u2 * (1.0f + erff(u2 * k));
    u3 = 0.5f * u3 * (1.0f + erff(u3 * k));

    if (FINAL) {
        const float4 w4 = __ldg(&((const float4*)Wh)[q]);
        float p = u0 * w4.x + u1 * w4.y + u2 * w4.z + u3 * w4.w;
#pragma unroll
        for (int o = 8; o > 0; o >>= 1) p += __shfl_xor_sync(0xffffffffu, p, o);
        if (lane == 0) out[node] = p + __ldg(&bh[0]);
    } else {
        if (h == 0)
            ((float4*)out)[(size_t)node * 16 + q] = make_float4(u0, u1, u2, u3);
    }
}

// ---------------- launch -----------------------------------------------------
extern "C" void kernel_launch(void* const* d_in, const int* in_sizes, int n_in,
                              void* d_out, int out_size) {
    const float* x   = (const float*)d_in[0];
    const int*   ei  = (const int*)d_in[1];
    const float* W1  = (const float*)d_in[2];
    const float* b1  = (const float*)d_in[3];
    const float* g1  = (const float*)d_in[4];
    const float* be1 = (const float*)d_in[5];
    const float* W2  = (const float*)d_in[6];
    const float* b2  = (const float*)d_in[7];
    const float* g2  = (const float*)d_in[8];
    const float* be2 = (const float*)d_in[9];
    const float* W3  = (const float*)d_in[10];
    const float* b3  = (const float*)d_in[11];
    const float* g3  = (const float*)d_in[12];
    const float* be3 = (const float*)d_in[13];
    const float* Wh  = (const float*)d_in[14];
    const float* bh  = (const float*)d_in[15];
    float* out = (float*)d_out;

    const int n = in_sizes[0] / 128;
    const int e = in_sizes[1] / 2;
    const int* srcs = ei;
    const int* dsts = ei + e;

    // smem bytes: 64*(K+4) + K*(HDIM+4) unsigned words
    const int SM128 = (64 * 132 + 128 * 68) * 4;   // 68608
    const int SM64  = (64 * 68 + 64 * 68) * 4;     // 34816

    static float* y = nullptr;
    if (!y) {
        cudaGetSymbolAddress((void**)&y, g_y);
        cudaFuncSetAttribute(gemm_tf32_kernel<128>,
                             cudaFuncAttributeMaxDynamicSharedMemorySize, SM128);
        cudaFuncSetAttribute(gemm_tf32_kernel<64>,
                             cudaFuncAttributeMaxDynamicSharedMemorySize, SM64);
    }

    const int EB = (e + 255) / 256;
    const int SB = (n + SCAN_B - 1) / SCAN_B;  // scan blocks (<= 98)
    const int GB = (n + 63) / 64;              // gemm blocks (64 rows/block)
    const int WB = (n + 7) / 8;                // gather blocks (8 warps/block)

    // CSR build (deg is zeroed at module load and re-zeroed by scanA)
    count_deg_kernel<<<EB, 256>>>(dsts, e);
    scanA_kernel<<<SB, SCAN_B>>>(n);           // + fused dinv + deg re-zero
    scanC_kernel<<<SB, SCAN_B>>>(n, e);        // + folded scanB + cursor init
    place_kernel<<<EB, 256>>>(srcs, dsts, e);

    // Layer 1 (IN=128)
    gemm_tf32_kernel<128><<<GB, 128, SM128>>>(x, W1, n);
    gather_finalize_kernel<false><<<WB, 256>>>(b1, g1, be1, nullptr, nullptr, y, n);
    // Layer 2 (IN=64)
    gemm_tf32_kernel<64><<<GB, 128, SM64>>>(y, W2, n);
    gather_finalize_kernel<false><<<WB, 256>>>(b2, g2, be2, nullptr, nullptr, y, n);
    // Layer 3 (IN=64) + fused head
    gemm_tf32_kernel<64><<<GB, 128, SM64>>>(y, W3, n);
    gather_finalize_kernel<true><<<WB, 256>>>(b3, g3, be3, Wh, bh, out, n);
}